// round 1
// baseline (speedup 1.0000x reference)
#include <cuda_runtime.h>
#include <cuda_bf16.h>
#include <cstdint>

#define BATCH 8
#define NPTS  8192
#define NCTR  2048          // NPTS * 0.25
#define NSAMP 32
#define C0IN  67
#define C0    64
#define C1    64
#define C2    128
#define R2    0.25f         // radius^2

// ---------------- scratch (device globals; no allocation allowed) ----------------
__device__ int   g_ballidx[BATCH * NCTR * NSAMP];            // 2 MB
__device__ float g_F0[(size_t)BATCH * NPTS * C0];            // 16 MB, layout (b, j, o)

// =====================================================================
// 1) Furthest point sampling: one block per batch, 1024 threads,
//    8 points per thread held in registers. Writes new_xyz directly
//    into d_out (first 8*2048*3 floats).
// =====================================================================
__global__ void __launch_bounds__(1024, 1)
fps_kernel(const float* __restrict__ pos, float* __restrict__ new_xyz)
{
    const int b = blockIdx.x;
    const int t = threadIdx.x;
    const float* pb = pos + (size_t)b * NPTS * 3;

    float x[8], y[8], z[8], dm[8];
#pragma unroll
    for (int j = 0; j < 8; j++) {
        int p = t + j * 1024;
        x[j] = pb[3 * p + 0];
        y[j] = pb[3 * p + 1];
        z[j] = pb[3 * p + 2];
        dm[j] = 1e10f;
    }

    __shared__ float s_px, s_py, s_pz;
    __shared__ unsigned s_wval[32];
    __shared__ unsigned s_widx[32];

    if (t == 0) {
        float qx = pb[0], qy = pb[1], qz = pb[2];
        s_px = qx; s_py = qy; s_pz = qz;
        float* nz = new_xyz + (size_t)b * NCTR * 3;
        nz[0] = qx; nz[1] = qy; nz[2] = qz;
    }
    __syncthreads();

    const int lane = t & 31, w = t >> 5;

    for (int s = 1; s < NCTR; ++s) {
        float px = s_px, py = s_py, pz = s_pz;

        float m = -1.0f;
        int jb = 0;
#pragma unroll
        for (int j = 0; j < 8; j++) {
            float dx = x[j] - px;
            float dy = y[j] - py;
            float dz = z[j] - pz;
            float d = fmaf(dz, dz, fmaf(dy, dy, dx * dx));
            dm[j] = fminf(dm[j], d);
            if (dm[j] > m) { m = dm[j]; jb = j; }
        }

        unsigned mb = __float_as_uint(m);                 // d >= 0: order-preserving
        unsigned wmax = __reduce_max_sync(0xffffffffu, mb);
        unsigned cand = (mb == wmax) ? (unsigned)(t + (jb << 10)) : 0xffffffffu;
        unsigned widx = __reduce_min_sync(0xffffffffu, cand);  // first-occurrence tie-break
        if (lane == 0) { s_wval[w] = wmax; s_widx[w] = widx; }
        __syncthreads();

        if (w == 0) {
            unsigned v = s_wval[lane];
            unsigned i = s_widx[lane];
            unsigned bmax = __reduce_max_sync(0xffffffffu, v);
            unsigned c2 = (v == bmax) ? i : 0xffffffffu;
            unsigned bidx = __reduce_min_sync(0xffffffffu, c2);
            if (lane == 0) {
                const float* pp = pb + (size_t)bidx * 3;
                float qx = pp[0], qy = pp[1], qz = pp[2];
                s_px = qx; s_py = qy; s_pz = qz;
                float* nz = new_xyz + ((size_t)b * NCTR + s) * 3;
                nz[0] = qx; nz[1] = qy; nz[2] = qz;
            }
        }
        __syncthreads();
    }
}

// =====================================================================
// 2) F0(b, j, o) = sum_c w0[o, 3+c] * features[b, c, j]
//    One thread per point j, 64 output channels in registers.
// =====================================================================
__global__ void __launch_bounds__(128)
f0_kernel(const float* __restrict__ features, const float* __restrict__ w0)
{
    __shared__ float w0t[64][64];   // w0t[c][o]
    const int tid = threadIdx.x;
    const int b = blockIdx.y;
    const int j = blockIdx.x * 128 + tid;

    for (int i = tid; i < 64 * 64; i += 128) {
        int c = i >> 6, o = i & 63;
        w0t[c][o] = w0[o * C0IN + 3 + c];
    }
    __syncthreads();

    float acc[64];
#pragma unroll
    for (int o = 0; o < 64; o++) acc[o] = 0.0f;

    for (int c = 0; c < 64; c++) {
        float fc = features[((size_t)b * 64 + c) * NPTS + j];
#pragma unroll
        for (int o4 = 0; o4 < 64; o4 += 4) {
            float4 wv = *(const float4*)&w0t[c][o4];
            acc[o4 + 0] = fmaf(wv.x, fc, acc[o4 + 0]);
            acc[o4 + 1] = fmaf(wv.y, fc, acc[o4 + 1]);
            acc[o4 + 2] = fmaf(wv.z, fc, acc[o4 + 2]);
            acc[o4 + 3] = fmaf(wv.w, fc, acc[o4 + 3]);
        }
    }

    float* op = g_F0 + ((size_t)b * NPTS + j) * 64;
#pragma unroll
    for (int o4 = 0; o4 < 64; o4 += 4) {
        float4 v = make_float4(acc[o4], acc[o4 + 1], acc[o4 + 2], acc[o4 + 3]);
        *(float4*)(op + o4) = v;
    }
}

// =====================================================================
// 3) Ball query: thread per center, first-32-in-index-order within radius,
//    pad with first hit (center itself always hits).
// =====================================================================
__global__ void __launch_bounds__(128)
ballq_kernel(const float* __restrict__ pos, const float* __restrict__ new_xyz)
{
    const int gid = blockIdx.x * 128 + threadIdx.x;
    const int b = gid >> 11;          // / 2048
    const int s = gid & 2047;

    const float* cz = new_xyz + (size_t)gid * 3;
    const float cx = cz[0], cy = cz[1], czz = cz[2];
    const float* pb = pos + (size_t)b * NPTS * 3;
    int* out = g_ballidx + (size_t)gid * NSAMP;

    int cnt = 0;
    int first = 0;
    for (int j = 0; j < NPTS; j++) {
        float dx = pb[3 * j + 0] - cx;
        float dy = pb[3 * j + 1] - cy;
        float dz = pb[3 * j + 2] - czz;
        float d = fmaf(dz, dz, fmaf(dy, dy, dx * dx));
        if (d < R2) {
            if (cnt == 0) first = j;
            out[cnt++] = j;
            if (cnt == NSAMP) break;
        }
    }
    for (int k = cnt; k < NSAMP; k++) out[k] = first;
}

// =====================================================================
// 4) Fused grouped MLP + max pool. 4 centers per block (128 rows of k),
//    all-fp32 register-tiled GEMMs in shared memory.
//    Thread map: tm = tid&31 (m0 = 4*tm), tn = tid>>5.
// =====================================================================
#define XROW 132                         // padded row stride for X tiles (16B aligned)
#define SMEM_FLOATS (4096 + 8192 + 64*XROW + 64*XROW + 256 + 64 + 128)

__global__ void __launch_bounds__(256, 1)
fused_mlp_kernel(const float* __restrict__ pos,
                 const float* __restrict__ new_xyz,
                 const float* __restrict__ w0, const float* __restrict__ b0,
                 const float* __restrict__ w1, const float* __restrict__ b1,
                 const float* __restrict__ w2, const float* __restrict__ b2,
                 float* __restrict__ out_feat)
{
    extern __shared__ float sm[];
    float* sW1 = sm;                       // [c][o] 64x64
    float* sW2 = sm + 4096;                // [c][o] 64x128
    float* sX0 = sm + 12288;               // [c][m] 64 x XROW
    float* sX1 = sm + 12288 + 64 * XROW;   // [c][m] 64 x XROW
    float4* sWXB = (float4*)(sm + 12288 + 128 * XROW);   // 64 x {w0x,w0y,w0z,b0}
    float* sB1 = sm + 12288 + 128 * XROW + 256;
    float* sB2 = sB1 + 64;

    const int tid = threadIdx.x;
    const int b = blockIdx.x >> 9;
    const int s0 = (blockIdx.x & 511) * 4;

    // ---- load weights (transposed) ----
    for (int i = tid; i < 4096; i += 256) {
        int c = i >> 6, o = i & 63;
        sW1[c * 64 + o] = w1[o * 64 + c];
    }
    for (int i = tid; i < 8192; i += 256) {
        int c = i >> 7, o = i & 127;
        sW2[c * 128 + o] = w2[o * 64 + c];
    }
    if (tid < 64) {
        sWXB[tid] = make_float4(w0[tid * C0IN + 0], w0[tid * C0IN + 1],
                                w0[tid * C0IN + 2], b0[tid]);
        sB1[tid] = b1[tid];
    }
    if (tid < 128) sB2[tid] = b2[tid];
    __syncthreads();

    // ---- phase A: build X0 (layer0 output) ----
    {
        const int r = tid >> 1;            // row 0..127
        const int h = tid & 1;
        const int o0 = h * 32;
        const int ci = r >> 5, k = r & 31;
        const int sg = s0 + ci;
        const int j = g_ballidx[(((size_t)b * NCTR + sg) << 5) + k];

        const float* pp = pos + ((size_t)b * NPTS + j) * 3;
        const float* cz = new_xyz + ((size_t)b * NCTR + sg) * 3;
        float rx = pp[0] - cz[0];
        float ry = pp[1] - cz[1];
        float rz = pp[2] - cz[2];
        const float* fp = g_F0 + ((size_t)b * NPTS + j) * 64 + o0;

#pragma unroll
        for (int o4 = 0; o4 < 32; o4 += 4) {
            float4 f = *(const float4*)(fp + o4);
            float fv[4] = { f.x, f.y, f.z, f.w };
#pragma unroll
            for (int i = 0; i < 4; i++) {
                float4 wb = sWXB[o0 + o4 + i];
                float v = fv[i] + wb.x * rx + wb.y * ry + wb.z * rz + wb.w;
                sX0[(o0 + o4 + i) * XROW + r] = fmaxf(v, 0.0f);
            }
        }
    }
    __syncthreads();

    const int tm = tid & 31, tn = tid >> 5;
    const int m0 = tm * 4;

    // ---- GEMM1: X1 = relu(X0 @ W1^T + b1), 128x64 ----
    {
        const int n0 = tn * 8;
        float acc[32];
#pragma unroll
        for (int i = 0; i < 32; i++) acc[i] = 0.0f;

#pragma unroll 8
        for (int c = 0; c < 64; c++) {
            float4 a = *(const float4*)&sX0[c * XROW + m0];
            float4 bA = *(const float4*)&sW1[c * 64 + n0];
            float4 bB = *(const float4*)&sW1[c * 64 + n0 + 4];
            float av[4] = { a.x, a.y, a.z, a.w };
            float bv[8] = { bA.x, bA.y, bA.z, bA.w, bB.x, bB.y, bB.z, bB.w };
#pragma unroll
            for (int i = 0; i < 4; i++)
#pragma unroll
                for (int jn = 0; jn < 8; jn++)
                    acc[i * 8 + jn] = fmaf(av[i], bv[jn], acc[i * 8 + jn]);
        }
#pragma unroll
        for (int jn = 0; jn < 8; jn++) {
            float bb = sB1[n0 + jn];
            float4 v;
            v.x = fmaxf(acc[0 * 8 + jn] + bb, 0.0f);
            v.y = fmaxf(acc[1 * 8 + jn] + bb, 0.0f);
            v.z = fmaxf(acc[2 * 8 + jn] + bb, 0.0f);
            v.w = fmaxf(acc[3 * 8 + jn] + bb, 0.0f);
            *(float4*)&sX1[(n0 + jn) * XROW + m0] = v;
        }
    }
    __syncthreads();

    // ---- GEMM2: Y = X1 @ W2^T, 128x128, fold max over k + bias + relu ----
    {
        const int n2 = tn * 16;
        float acc[64];
#pragma unroll
        for (int i = 0; i < 64; i++) acc[i] = 0.0f;

#pragma unroll 4
        for (int c = 0; c < 64; c++) {
            float4 a = *(const float4*)&sX1[c * XROW + m0];
            float av[4] = { a.x, a.y, a.z, a.w };
            float bv[16];
#pragma unroll
            for (int q = 0; q < 4; q++) {
                float4 bb = *(const float4*)&sW2[c * 128 + n2 + 4 * q];
                bv[4 * q + 0] = bb.x; bv[4 * q + 1] = bb.y;
                bv[4 * q + 2] = bb.z; bv[4 * q + 3] = bb.w;
            }
#pragma unroll
            for (int i = 0; i < 4; i++)
#pragma unroll
                for (int jn = 0; jn < 16; jn++)
                    acc[i * 16 + jn] = fmaf(av[i], bv[jn], acc[i * 16 + jn]);
        }

        const int center = tm >> 3;   // 4 rows per thread stay within one center
#pragma unroll
        for (int jn = 0; jn < 16; jn++) {
            float v = fmaxf(fmaxf(acc[0 * 16 + jn], acc[1 * 16 + jn]),
                            fmaxf(acc[2 * 16 + jn], acc[3 * 16 + jn]));
            v = fmaxf(v, __shfl_xor_sync(0xffffffffu, v, 1));
            v = fmaxf(v, __shfl_xor_sync(0xffffffffu, v, 2));
            v = fmaxf(v, __shfl_xor_sync(0xffffffffu, v, 4));
            if ((tm & 7) == 0) {
                int n = n2 + jn;
                out_feat[((size_t)b * C2 + n) * NCTR + (s0 + center)] =
                    fmaxf(v + sB2[n], 0.0f);
            }
        }
    }
}

// =====================================================================
extern "C" void kernel_launch(void* const* d_in, const int* in_sizes, int n_in,
                              void* d_out, int out_size)
{
    const float* pos      = (const float*)d_in[0];
    const float* features = (const float*)d_in[1];
    const float* w0       = (const float*)d_in[2];
    const float* b0       = (const float*)d_in[3];
    const float* w1       = (const float*)d_in[4];
    const float* b1       = (const float*)d_in[5];
    const float* w2       = (const float*)d_in[6];
    const float* b2       = (const float*)d_in[7];

    float* out = (float*)d_out;
    float* new_xyz  = out;                               // (8, 2048, 3)
    float* out_feat = out + (size_t)BATCH * NCTR * 3;    // (8, 128, 2048)

    fps_kernel<<<BATCH, 1024>>>(pos, new_xyz);
    f0_kernel<<<dim3(NPTS / 128, BATCH), 128>>>(features, w0);
    ballq_kernel<<<(BATCH * NCTR) / 128, 128>>>(pos, new_xyz);

    cudaFuncSetAttribute(fused_mlp_kernel,
                         cudaFuncAttributeMaxDynamicSharedMemorySize,
                         SMEM_FLOATS * sizeof(float));
    fused_mlp_kernel<<<BATCH * NCTR / 4, 256, SMEM_FLOATS * sizeof(float)>>>(
        pos, new_xyz, w0, b0, w1, b1, w2, b2, out_feat);
}

// round 2
// speedup vs baseline: 1.0743x; 1.0743x over previous
#include <cuda_runtime.h>
#include <cuda_bf16.h>
#include <cstdint>

#define BATCH 8
#define NPTS  8192
#define NCTR  2048          // NPTS * 0.25
#define NSAMP 32
#define C0IN  67
#define C0    64
#define C1    64
#define C2    128
#define R2    0.25f         // radius^2

// ---------------- scratch (device globals; no allocation allowed) ----------------
__device__ int   g_ballidx[BATCH * NCTR * NSAMP];            // 2 MB
__device__ float g_F0[(size_t)BATCH * NPTS * C0];            // 16 MB, layout (b, j, o)

// ---------------- f32x2 packed helpers ----------------
__device__ __forceinline__ unsigned long long pk2(float lo, float hi) {
    unsigned long long r;
    asm("mov.b64 %0, {%1, %2};" : "=l"(r) : "f"(lo), "f"(hi));
    return r;
}
__device__ __forceinline__ unsigned long long pkb(float v) { return pk2(v, v); }
__device__ __forceinline__ void upk2(unsigned long long v, float& lo, float& hi) {
    asm("mov.b64 {%0, %1}, %2;" : "=f"(lo), "=f"(hi) : "l"(v));
}
#define F2FMA(d, a, b, c) asm("fma.rn.f32x2 %0, %1, %2, %3;" : "=l"(d) : "l"(a), "l"(b), "l"(c))
#define F2ADD(d, a, b)    asm("add.rn.f32x2 %0, %1, %2;"     : "=l"(d) : "l"(a), "l"(b))
#define F2MUL(d, a, b)    asm("mul.rn.f32x2 %0, %1, %2;"     : "=l"(d) : "l"(a), "l"(b))

// =====================================================================
// 1) Furthest point sampling: one block per batch, 512 threads,
//    16 points per thread in registers, f32x2-packed distance update,
//    lazy index resolution via shared atomicMin.
// =====================================================================
__global__ void __launch_bounds__(512, 1)
fps_kernel(const float* __restrict__ pos, float* __restrict__ new_xyz)
{
    const int b = blockIdx.x;
    const int t = threadIdx.x;
    const float* pb = pos + (size_t)b * NPTS * 3;

    unsigned long long xp[8], yp[8], zp[8];
    float dm[16];
#pragma unroll
    for (int k = 0; k < 8; k++) {
        int p0 = t + (2 * k) * 512;
        int p1 = p0 + 512;
        xp[k] = pk2(pb[3 * p0 + 0], pb[3 * p1 + 0]);
        yp[k] = pk2(pb[3 * p0 + 1], pb[3 * p1 + 1]);
        zp[k] = pk2(pb[3 * p0 + 2], pb[3 * p1 + 2]);
        dm[2 * k] = 1e10f; dm[2 * k + 1] = 1e10f;
    }

    __shared__ unsigned s_wval[16];
    __shared__ int s_idx[2];

    float cx = pb[0], cy = pb[1], cz = pb[2];
    if (t == 0) {
        s_idx[0] = 0x7fffffff;
        s_idx[1] = 0x7fffffff;
        float* nz = new_xyz + (size_t)b * NCTR * 3;
        nz[0] = cx; nz[1] = cy; nz[2] = cz;
    }
    __syncthreads();

    const int lane = t & 31, w = t >> 5;

    for (int s = 1; s < NCTR; ++s) {
        const unsigned long long nx = pkb(-cx);
        const unsigned long long ny = pkb(-cy);
        const unsigned long long nz2 = pkb(-cz);

        float m = 0.0f;
#pragma unroll
        for (int k = 0; k < 8; k++) {
            unsigned long long dx, dy, dz, sq;
            F2ADD(dx, xp[k], nx);
            F2ADD(dy, yp[k], ny);
            F2ADD(dz, zp[k], nz2);
            F2MUL(sq, dx, dx);                       // dx*dx
            F2FMA(sq, dy, dy, sq);                   // fma(dy,dy, dx*dx)
            F2FMA(sq, dz, dz, sq);                   // fma(dz,dz, ...)  (== round-1 scalar chain)
            float lo, hi; upk2(sq, lo, hi);
            dm[2 * k]     = fminf(dm[2 * k], lo);
            dm[2 * k + 1] = fminf(dm[2 * k + 1], hi);
            m = fmaxf(m, dm[2 * k]);
            m = fmaxf(m, dm[2 * k + 1]);
        }

        unsigned mb = __float_as_uint(m);            // d >= 0: order-preserving
        unsigned wmax = __reduce_max_sync(0xffffffffu, mb);
        if (lane == 0) s_wval[w] = wmax;
        const int buf = s & 1;
        __syncthreads();                             // bar1

        if (t == 0) s_idx[buf ^ 1] = 0x7fffffff;     // reset buffer for step s+1

        unsigned v = (lane < 16) ? s_wval[lane] : 0u;
        unsigned gmax = __reduce_max_sync(0xffffffffu, v);

        if (mb == gmax) {                            // this thread holds (one of) the maxima
            int best = 0x7fffffff;
#pragma unroll
            for (int j = 15; j >= 0; j--)
                if (__float_as_uint(dm[j]) == gmax) best = (j << 9) + t;   // point index = t + j*512
            atomicMin(&s_idx[buf], best);            // global min index = first occurrence
        }
        __syncthreads();                             // bar2

        const int widx = s_idx[buf];
        const float* pp = pb + 3 * (size_t)widx;
        cx = pp[0]; cy = pp[1]; cz = pp[2];
        if (t == 0) {
            float* nz = new_xyz + ((size_t)b * NCTR + s) * 3;
            nz[0] = cx; nz[1] = cy; nz[2] = cz;
        }
    }
}

// =====================================================================
// 2) F0(b, j, o) = sum_c w0[o, 3+c] * features[b, c, j]
// =====================================================================
__global__ void __launch_bounds__(128)
f0_kernel(const float* __restrict__ features, const float* __restrict__ w0)
{
    __shared__ float w0t[64][64];   // w0t[c][o]
    const int tid = threadIdx.x;
    const int b = blockIdx.y;
    const int j = blockIdx.x * 128 + tid;

    for (int i = tid; i < 64 * 64; i += 128) {
        int c = i >> 6, o = i & 63;
        w0t[c][o] = w0[o * C0IN + 3 + c];
    }
    __syncthreads();

    float acc[64];
#pragma unroll
    for (int o = 0; o < 64; o++) acc[o] = 0.0f;

    for (int c = 0; c < 64; c++) {
        float fc = features[((size_t)b * 64 + c) * NPTS + j];
#pragma unroll
        for (int o4 = 0; o4 < 64; o4 += 4) {
            float4 wv = *(const float4*)&w0t[c][o4];
            acc[o4 + 0] = fmaf(wv.x, fc, acc[o4 + 0]);
            acc[o4 + 1] = fmaf(wv.y, fc, acc[o4 + 1]);
            acc[o4 + 2] = fmaf(wv.z, fc, acc[o4 + 2]);
            acc[o4 + 3] = fmaf(wv.w, fc, acc[o4 + 3]);
        }
    }

    float* op = g_F0 + ((size_t)b * NPTS + j) * 64;
#pragma unroll
    for (int o4 = 0; o4 < 64; o4 += 4) {
        float4 v = make_float4(acc[o4], acc[o4 + 1], acc[o4 + 2], acc[o4 + 3]);
        *(float4*)(op + o4) = v;
    }
}

// =====================================================================
// 3) Ball query
// =====================================================================
__global__ void __launch_bounds__(128)
ballq_kernel(const float* __restrict__ pos, const float* __restrict__ new_xyz)
{
    const int gid = blockIdx.x * 128 + threadIdx.x;
    const int b = gid >> 11;          // / 2048

    const float* cz = new_xyz + (size_t)gid * 3;
    const float cx = cz[0], cy = cz[1], czz = cz[2];
    const float* pb = pos + (size_t)b * NPTS * 3;
    int* out = g_ballidx + (size_t)gid * NSAMP;

    int cnt = 0;
    int first = 0;
    for (int j = 0; j < NPTS; j++) {
        float dx = pb[3 * j + 0] - cx;
        float dy = pb[3 * j + 1] - cy;
        float dz = pb[3 * j + 2] - czz;
        float d = fmaf(dz, dz, fmaf(dy, dy, dx * dx));
        if (d < R2) {
            if (cnt == 0) first = j;
            out[cnt++] = j;
            if (cnt == NSAMP) break;
        }
    }
    for (int k = cnt; k < NSAMP; k++) out[k] = first;
}

// =====================================================================
// 4) Fused grouped MLP + max pool, now with fma.rn.f32x2 GEMM cores.
// =====================================================================
#define XROW 132
#define SMEM_FLOATS (4096 + 8192 + 64*XROW + 64*XROW + 256 + 64 + 128)

__global__ void __launch_bounds__(256, 1)
fused_mlp_kernel(const float* __restrict__ pos,
                 const float* __restrict__ new_xyz,
                 const float* __restrict__ w0, const float* __restrict__ b0,
                 const float* __restrict__ w1, const float* __restrict__ b1,
                 const float* __restrict__ w2, const float* __restrict__ b2,
                 float* __restrict__ out_feat)
{
    extern __shared__ float sm[];
    float* sW1 = sm;                       // [c][o] 64x64
    float* sW2 = sm + 4096;                // [c][o] 64x128
    float* sX0 = sm + 12288;               // [c][m] 64 x XROW
    float* sX1 = sm + 12288 + 64 * XROW;   // [c][m] 64 x XROW
    float4* sWXB = (float4*)(sm + 12288 + 128 * XROW);   // 64 x {w0x,w0y,w0z,b0}
    float* sB1 = sm + 12288 + 128 * XROW + 256;
    float* sB2 = sB1 + 64;

    const int tid = threadIdx.x;
    const int b = blockIdx.x >> 9;
    const int s0 = (blockIdx.x & 511) * 4;

    // ---- load weights (transposed) ----
    for (int i = tid; i < 4096; i += 256) {
        int c = i >> 6, o = i & 63;
        sW1[c * 64 + o] = w1[o * 64 + c];
    }
    for (int i = tid; i < 8192; i += 256) {
        int c = i >> 7, o = i & 127;
        sW2[c * 128 + o] = w2[o * 64 + c];
    }
    if (tid < 64) {
        sWXB[tid] = make_float4(w0[tid * C0IN + 0], w0[tid * C0IN + 1],
                                w0[tid * C0IN + 2], b0[tid]);
        sB1[tid] = b1[tid];
    }
    if (tid < 128) sB2[tid] = b2[tid];
    __syncthreads();

    // ---- phase A: build X0 (layer0 output) ----
    {
        const int r = tid >> 1;            // row 0..127
        const int h = tid & 1;
        const int o0 = h * 32;
        const int ci = r >> 5, k = r & 31;
        const int sg = s0 + ci;
        const int j = g_ballidx[(((size_t)b * NCTR + sg) << 5) + k];

        const float* pp = pos + ((size_t)b * NPTS + j) * 3;
        const float* cz = new_xyz + ((size_t)b * NCTR + sg) * 3;
        float rx = pp[0] - cz[0];
        float ry = pp[1] - cz[1];
        float rz = pp[2] - cz[2];
        const float* fp = g_F0 + ((size_t)b * NPTS + j) * 64 + o0;

#pragma unroll
        for (int o4 = 0; o4 < 32; o4 += 4) {
            float4 f = *(const float4*)(fp + o4);
            float fv[4] = { f.x, f.y, f.z, f.w };
#pragma unroll
            for (int i = 0; i < 4; i++) {
                float4 wb = sWXB[o0 + o4 + i];
                float v = fv[i] + wb.x * rx + wb.y * ry + wb.z * rz + wb.w;
                sX0[(o0 + o4 + i) * XROW + r] = fmaxf(v, 0.0f);
            }
        }
    }
    __syncthreads();

    const int tm = tid & 31, tn = tid >> 5;
    const int m0 = tm * 4;

    // ---- GEMM1: X1 = relu(X0 @ W1^T + b1), 128x64, f32x2 packed ----
    {
        const int n0 = tn * 8;
        unsigned long long acc2[16];
#pragma unroll
        for (int i = 0; i < 16; i++) acc2[i] = 0ULL;

#pragma unroll 8
        for (int c = 0; c < 64; c++) {
            float4 a  = *(const float4*)&sX0[c * XROW + m0];
            float4 bA = *(const float4*)&sW1[c * 64 + n0];
            float4 bB = *(const float4*)&sW1[c * 64 + n0 + 4];
            unsigned long long bp[4] = { pk2(bA.x, bA.y), pk2(bA.z, bA.w),
                                         pk2(bB.x, bB.y), pk2(bB.z, bB.w) };
            unsigned long long ap[4] = { pkb(a.x), pkb(a.y), pkb(a.z), pkb(a.w) };
#pragma unroll
            for (int i = 0; i < 4; i++)
#pragma unroll
                for (int jp = 0; jp < 4; jp++)
                    F2FMA(acc2[i * 4 + jp], ap[i], bp[jp], acc2[i * 4 + jp]);
        }

#pragma unroll
        for (int jp = 0; jp < 4; jp++) {
            float lo[4], hi[4];
#pragma unroll
            for (int i = 0; i < 4; i++) upk2(acc2[i * 4 + jp], lo[i], hi[i]);
            float bb0 = sB1[n0 + 2 * jp], bb1 = sB1[n0 + 2 * jp + 1];
            float4 v0, v1;
            v0.x = fmaxf(lo[0] + bb0, 0.0f); v0.y = fmaxf(lo[1] + bb0, 0.0f);
            v0.z = fmaxf(lo[2] + bb0, 0.0f); v0.w = fmaxf(lo[3] + bb0, 0.0f);
            v1.x = fmaxf(hi[0] + bb1, 0.0f); v1.y = fmaxf(hi[1] + bb1, 0.0f);
            v1.z = fmaxf(hi[2] + bb1, 0.0f); v1.w = fmaxf(hi[3] + bb1, 0.0f);
            *(float4*)&sX1[(n0 + 2 * jp)     * XROW + m0] = v0;
            *(float4*)&sX1[(n0 + 2 * jp + 1) * XROW + m0] = v1;
        }
    }
    __syncthreads();

    // ---- GEMM2: Y = X1 @ W2^T, 128x128, f32x2 packed, fold max+bias+relu ----
    {
        const int n2 = tn * 16;
        unsigned long long acc2[32];
#pragma unroll
        for (int i = 0; i < 32; i++) acc2[i] = 0ULL;

#pragma unroll 4
        for (int c = 0; c < 64; c++) {
            float4 a = *(const float4*)&sX1[c * XROW + m0];
            unsigned long long ap[4] = { pkb(a.x), pkb(a.y), pkb(a.z), pkb(a.w) };
            unsigned long long bp[8];
#pragma unroll
            for (int q = 0; q < 4; q++) {
                float4 bb = *(const float4*)&sW2[c * 128 + n2 + 4 * q];
                bp[2 * q]     = pk2(bb.x, bb.y);
                bp[2 * q + 1] = pk2(bb.z, bb.w);
            }
#pragma unroll
            for (int i = 0; i < 4; i++)
#pragma unroll
                for (int jp = 0; jp < 8; jp++)
                    F2FMA(acc2[i * 8 + jp], ap[i], bp[jp], acc2[i * 8 + jp]);
        }

        const int center = tm >> 3;   // 4 rows per thread stay within one center
#pragma unroll
        for (int jp = 0; jp < 8; jp++) {
            float lo[4], hi[4];
#pragma unroll
            for (int i = 0; i < 4; i++) upk2(acc2[i * 8 + jp], lo[i], hi[i]);
            float vlo = fmaxf(fmaxf(lo[0], lo[1]), fmaxf(lo[2], lo[3]));
            float vhi = fmaxf(fmaxf(hi[0], hi[1]), fmaxf(hi[2], hi[3]));
            vlo = fmaxf(vlo, __shfl_xor_sync(0xffffffffu, vlo, 1));
            vhi = fmaxf(vhi, __shfl_xor_sync(0xffffffffu, vhi, 1));
            vlo = fmaxf(vlo, __shfl_xor_sync(0xffffffffu, vlo, 2));
            vhi = fmaxf(vhi, __shfl_xor_sync(0xffffffffu, vhi, 2));
            vlo = fmaxf(vlo, __shfl_xor_sync(0xffffffffu, vlo, 4));
            vhi = fmaxf(vhi, __shfl_xor_sync(0xffffffffu, vhi, 4));
            if ((tm & 7) == 0) {
                int n = n2 + 2 * jp;
                out_feat[((size_t)b * C2 + n)     * NCTR + (s0 + center)] =
                    fmaxf(vlo + sB2[n], 0.0f);
                out_feat[((size_t)b * C2 + n + 1) * NCTR + (s0 + center)] =
                    fmaxf(vhi + sB2[n + 1], 0.0f);
            }
        }
    }
}

// =====================================================================
extern "C" void kernel_launch(void* const* d_in, const int* in_sizes, int n_in,
                              void* d_out, int out_size)
{
    const float* pos      = (const float*)d_in[0];
    const float* features = (const float*)d_in[1];
    const float* w0       = (const float*)d_in[2];
    const float* b0       = (const float*)d_in[3];
    const float* w1       = (const float*)d_in[4];
    const float* b1       = (const float*)d_in[5];
    const float* w2       = (const float*)d_in[6];
    const float* b2       = (const float*)d_in[7];

    float* out = (float*)d_out;
    float* new_xyz  = out;                               // (8, 2048, 3)
    float* out_feat = out + (size_t)BATCH * NCTR * 3;    // (8, 128, 2048)

    fps_kernel<<<BATCH, 512>>>(pos, new_xyz);
    f0_kernel<<<dim3(NPTS / 128, BATCH), 128>>>(features, w0);
    ballq_kernel<<<(BATCH * NCTR) / 128, 128>>>(pos, new_xyz);

    cudaFuncSetAttribute(fused_mlp_kernel,
                         cudaFuncAttributeMaxDynamicSharedMemorySize,
                         SMEM_FLOATS * sizeof(float));
    fused_mlp_kernel<<<BATCH * NCTR / 4, 256, SMEM_FLOATS * sizeof(float)>>>(
        pos, new_xyz, w0, b0, w1, b1, w2, b2, out_feat);
}